// round 3
// baseline (speedup 1.0000x reference)
#include <cuda_runtime.h>
#include <math.h>

#define GN 3136          // H*W
#define CC 384
#define BB 8
#define NHEADS 8
#define HD 48
#define SZ (BB*CC*GN)    // 9,633,792

// ---------------- scratch (static device globals; no runtime alloc) ----------------
__device__ __align__(16) float g_bufA[SZ];
__device__ __align__(16) float g_bufB[SZ];
__device__ __align__(16) float g_x1b[SZ];
__device__ __align__(16) float g_x2b[SZ];
__device__ __align__(16) float g_qkvb[3*SZ];
__device__ __align__(16) float g_hmid[4*SZ];
__device__ __align__(16) float g_w1f[CC*CC];
__device__ __align__(16) float g_b1f[CC];
__device__ __align__(16) float g_dwf[CC*9];
__device__ __align__(16) float g_dbf[CC];
__device__ __align__(16) float g_w1t[CC*4*CC];
__device__ __align__(16) float g_w2t[CC*4*CC];
__device__ __align__(16) float g_kv[BB*NHEADS*HD*HD];
__device__ __align__(16) float g_ksum[BB*NHEADS*HD];

// ---------------- BN folding ----------------
// w1f[o,i] = cw1[o,i]*s[i]; b1f[o] = cb1[o] + sum_i cw1[o,i]*t[i]
__global__ void fold_bn1_kernel(const float* __restrict__ cw1, const float* __restrict__ cb1,
                                const float* __restrict__ w, const float* __restrict__ bvec,
                                const float* __restrict__ m, const float* __restrict__ v) {
    int o = blockIdx.x;
    int tid = threadIdx.x;   // 128
    float part = 0.f;
    for (int i = tid; i < CC; i += 128) {
        float s = w[i] * rsqrtf(v[i] + 1e-5f);
        float t = bvec[i] - m[i] * s;
        float cv = cw1[o*CC + i];
        g_w1f[o*CC + i] = cv * s;
        part += cv * t;
    }
    __shared__ float red[128];
    red[tid] = part; __syncthreads();
    for (int st = 64; st > 0; st >>= 1) { if (tid < st) red[tid] += red[tid+st]; __syncthreads(); }
    if (tid == 0) g_b1f[o] = cb1[o] + red[0];
}

// fold BN2 into depthwise: dwf = dw*s2, dbf = db*s2 + t2
__global__ void fold_bn2_kernel(const float* __restrict__ dw, const float* __restrict__ db,
                                const float* __restrict__ w, const float* __restrict__ bvec,
                                const float* __restrict__ m, const float* __restrict__ v) {
    int c = blockIdx.x * blockDim.x + threadIdx.x;
    if (c < CC) {
        float s = w[c] * rsqrtf(v[c] + 1e-5f);
        float t = bvec[c] - m[c] * s;
        #pragma unroll
        for (int k = 0; k < 9; k++) g_dwf[c*9 + k] = dw[c*9 + k] * s;
        g_dbf[c] = db[c] * s + t;
    }
}

// dst[a*srows + b] = src[b*scols + a]   (src: srows x scols, dst: scols x srows)
__global__ void transpose_kernel(const float* __restrict__ src, float* __restrict__ dst,
                                 int srows, int scols) {
    int idx = blockIdx.x * 256 + threadIdx.x;
    if (idx < srows * scols) {
        int a = idx / srows;
        int b = idx - a * srows;
        dst[idx] = src[b * scols + a];
    }
}

__global__ void zero_kv_kernel() {
    int i = blockIdx.x * 256 + threadIdx.x;
    if (i < BB*NHEADS*HD*HD) g_kv[i] = 0.f;
    if (i < BB*NHEADS*HD)    g_ksum[i] = 0.f;
}

// ---------------- generic fp32 GEMM: Y[b,o,n] = act(W[o,:]·X[b,:,n] + bias[o]) (+ res) ----
// W: (Cout x K) row-major; X,Y,res per-batch (chan x GN). BM=128 BN=64 BK=16, 256 thr, 8x4.
template<int ACT>
__global__ __launch_bounds__(256)
void gemm_kernel(const float* __restrict__ W, const float* __restrict__ X,
                 const float* __restrict__ bias, const float* __restrict__ res,
                 float* __restrict__ Y, int Cout, int K) {
    const int b  = blockIdx.z;
    const int m0 = blockIdx.y * 128;
    const int n0 = blockIdx.x * 64;
    const float* Xb = X + (size_t)b * K * GN;
    float* Yb = Y + (size_t)b * Cout * GN;
    const float* Rb = res ? res + (size_t)b * Cout * GN : nullptr;

    __shared__ float As[16][128];
    __shared__ float Bs[16][64];

    const int tid = threadIdx.x;
    const int tm = tid >> 4;          // 0..15 -> 8 rows
    const int tn = tid & 15;          // 0..15 -> 4 cols

    float acc[8][4];
    #pragma unroll
    for (int i = 0; i < 8; i++)
        #pragma unroll
        for (int j = 0; j < 4; j++) acc[i][j] = 0.f;

    const int ar0 = tid >> 2;         // A rows: ar0, ar0+64
    const int akc = (tid & 3) * 4;    // A k-offset
    const int bk  = tid >> 4;         // B k row
    const int bn4 = (tid & 15) * 4;   // B col (float4)

    for (int k0 = 0; k0 < K; k0 += 16) {
        #pragma unroll
        for (int h = 0; h < 2; h++) {
            int row = ar0 + h * 64;
            float4 a4 = *reinterpret_cast<const float4*>(&W[(size_t)(m0 + row) * K + k0 + akc]);
            As[akc+0][row] = a4.x; As[akc+1][row] = a4.y;
            As[akc+2][row] = a4.z; As[akc+3][row] = a4.w;
        }
        float4 b4 = *reinterpret_cast<const float4*>(&Xb[(size_t)(k0 + bk) * GN + n0 + bn4]);
        *reinterpret_cast<float4*>(&Bs[bk][bn4]) = b4;
        __syncthreads();

        #pragma unroll
        for (int kk = 0; kk < 16; kk++) {
            float4 a0 = *reinterpret_cast<float4*>(&As[kk][tm*8]);
            float4 a1 = *reinterpret_cast<float4*>(&As[kk][tm*8 + 4]);
            float4 bbv = *reinterpret_cast<float4*>(&Bs[kk][tn*4]);
            float av[8] = {a0.x,a0.y,a0.z,a0.w,a1.x,a1.y,a1.z,a1.w};
            float bv[4] = {bbv.x,bbv.y,bbv.z,bbv.w};
            #pragma unroll
            for (int i = 0; i < 8; i++)
                #pragma unroll
                for (int j = 0; j < 4; j++)
                    acc[i][j] = fmaf(av[i], bv[j], acc[i][j]);
        }
        __syncthreads();
    }

    #pragma unroll
    for (int i = 0; i < 8; i++) {
        int m = m0 + tm*8 + i;
        float bval = bias ? bias[m] : 0.f;
        size_t off = (size_t)m * GN + n0 + tn*4;
        float4 r4 = make_float4(0.f,0.f,0.f,0.f);
        if (Rb) r4 = *reinterpret_cast<const float4*>(&Rb[off]);
        const float* rp = reinterpret_cast<const float*>(&r4);
        float o[4];
        #pragma unroll
        for (int j = 0; j < 4; j++) {
            float t = acc[i][j] + bval;
            if (ACT == 1) t = 0.5f * t * (1.f + erff(t * 0.70710678118654752f));
            if (Rb) t += rp[j];
            o[j] = t;
        }
        *reinterpret_cast<float4*>(&Yb[off]) = make_float4(o[0], o[1], o[2], o[3]);
    }
}

static void run_gemm(const float* W, const float* X, const float* bias, const float* res,
                     float* Y, int Cout, int K, int act) {
    dim3 g(GN/64, Cout/128, BB), blk(256);
    if (act) gemm_kernel<1><<<g, blk>>>(W, X, bias, res, Y, Cout, K);
    else     gemm_kernel<0><<<g, blk>>>(W, X, bias, res, Y, Cout, K);
}

// ---------------- depthwise 3x3 (BN2-folded weights/bias) ----------------
__global__ __launch_bounds__(256)
void dwconv_kernel(const float* __restrict__ in, float* __restrict__ out) {
    int bc = blockIdx.x;          // b*CC + c
    int c  = bc % CC;
    __shared__ float tile[58*58];
    const float* plane = in + (size_t)bc * GN;
    int tid = threadIdx.x;
    for (int idx = tid; idx < 58*58; idx += 256) {
        int ty = idx / 58, tx = idx - ty*58;
        int y = ty - 1, xq = tx - 1;
        float v = 0.f;
        if (y >= 0 && y < 56 && xq >= 0 && xq < 56) v = plane[y*56 + xq];
        tile[idx] = v;
    }
    __syncthreads();
    float w0=g_dwf[c*9+0], w1=g_dwf[c*9+1], w2=g_dwf[c*9+2];
    float w3=g_dwf[c*9+3], w4=g_dwf[c*9+4], w5=g_dwf[c*9+5];
    float w6=g_dwf[c*9+6], w7=g_dwf[c*9+7], w8=g_dwf[c*9+8];
    float bbv = g_dbf[c];
    float* oplane = out + (size_t)bc * GN;
    for (int p = tid; p < GN; p += 256) {
        int y = p / 56, xq = p - y*56;
        const float* t = &tile[y*58 + xq];
        float a = bbv + w0*t[0] + w1*t[1] + w2*t[2]
                      + w3*t[58] + w4*t[59] + w5*t[60]
                      + w6*t[116] + w7*t[117] + w8*t[118];
        oplane[p] = a;
    }
}

// ---------------- linear attention ----------------
__device__ __forceinline__ float phi_f(float t) { return expf(0.5f * (2.f*t - t*t)); }

// kv[d,e] = sum_n phi(k[n,d]) * v[n,e];  ksum[d] = sum_n phi(k[n,d])
__global__ __launch_bounds__(256)
void attn_kv_kernel(const float* __restrict__ qkv) {
    int bh = blockIdx.x; int b = bh >> 3, hd = bh & 7;
    int n0 = blockIdx.y * 392;
    __shared__ float kp_s[28*48];
    __shared__ float vv_s[28*48];
    int tid = threadIdx.x;
    int dr[9], er[9];
    #pragma unroll
    for (int r = 0; r < 9; r++) { int de = tid + 256*r; dr[r] = de/48; er[r] = de - dr[r]*48; }
    float acc[9];
    #pragma unroll
    for (int r = 0; r < 9; r++) acc[r] = 0.f;
    float ks = 0.f;
    const float* kbase = qkv + ((size_t)(b*1152 + CC   + hd*HD)) * GN + n0;
    const float* vbase = qkv + ((size_t)(b*1152 + 2*CC + hd*HD)) * GN + n0;
    for (int j0 = 0; j0 < 392; j0 += 28) {
        for (int idx = tid; idx < 48*28; idx += 256) {
            int d = idx / 28, j = idx - d*28;
            float kvl = kbase[(size_t)d*GN + j0 + j];
            kp_s[j*48 + d] = phi_f(kvl);
            vv_s[j*48 + d] = vbase[(size_t)d*GN + j0 + j];
        }
        __syncthreads();
        #pragma unroll 4
        for (int j = 0; j < 28; j++) {
            #pragma unroll
            for (int r = 0; r < 9; r++)
                acc[r] = fmaf(kp_s[j*48 + dr[r]], vv_s[j*48 + er[r]], acc[r]);
        }
        if (tid < 48) {
            float s = 0.f;
            #pragma unroll 4
            for (int j = 0; j < 28; j++) s += kp_s[j*48 + tid];
            ks += s;
        }
        __syncthreads();
    }
    #pragma unroll
    for (int r = 0; r < 9; r++) atomicAdd(&g_kv[bh*2304 + tid + 256*r], acc[r]);
    if (tid < 48) atomicAdd(&g_ksum[bh*48 + tid], ks);
}

// out[b, hd*48+e, n] = (sum_d phi(q[n,d]) kv[d,e]) / (phi(q[n,:])·ksum + eps)
__global__ __launch_bounds__(256)
void attn_out_kernel(const float* __restrict__ qkv, float* __restrict__ outp) {
    int bh = blockIdx.x; int b = bh >> 3, hd = bh & 7;
    int n0 = blockIdx.y * 392;
    __shared__ float kv_s[2304];
    __shared__ float ks_s[48];
    __shared__ float qp_s[28*49];
    __shared__ float dinv[28];
    int tid = threadIdx.x;
    for (int i = tid; i < 2304; i += 256) kv_s[i] = g_kv[bh*2304 + i];
    if (tid < 48) ks_s[tid] = g_ksum[bh*48 + tid];
    __syncthreads();
    const float* qbase = qkv + ((size_t)(b*1152 + hd*HD)) * GN + n0;
    float* obase = outp + ((size_t)(b*CC + hd*HD)) * GN + n0;
    for (int j0 = 0; j0 < 392; j0 += 28) {
        for (int idx = tid; idx < 48*28; idx += 256) {
            int d = idx / 28, j = idx - d*28;
            float q = qbase[(size_t)d*GN + j0 + j];
            qp_s[j*49 + d] = phi_f(q);
        }
        __syncthreads();
        if (tid < 28) {
            float s = 0.f;
            #pragma unroll
            for (int d = 0; d < 48; d++) s = fmaf(qp_s[tid*49 + d], ks_s[d], s);
            dinv[tid] = 1.f / (s + 1e-6f);
        }
        __syncthreads();
        for (int idx = tid; idx < 48*28; idx += 256) {
            int e = idx / 28, j = idx - e*28;
            float s = 0.f;
            #pragma unroll
            for (int d = 0; d < 48; d++) s = fmaf(qp_s[j*49 + d], kv_s[d*48 + e], s);
            obase[(size_t)e*GN + j0 + j] = s * dinv[j];
        }
        __syncthreads();
    }
}

// ---------------- LayerNorm over channels ----------------
__global__ __launch_bounds__(256)
void ln_kernel(const float* __restrict__ x2, const float* __restrict__ lw,
               const float* __restrict__ lb, float* __restrict__ xn) {
    int b = blockIdx.y; int n0 = blockIdx.x * 16;
    __shared__ float s[CC*17];
    __shared__ float r1[256], r2[256];
    __shared__ float mu[16], ri[16];
    const float* base = x2 + (size_t)b * CC * GN + n0;
    int tid = threadIdx.x;
    for (int idx = tid; idx < CC*16; idx += 256) {
        int c = idx >> 4, j = idx & 15;
        s[c*17 + j] = base[(size_t)c * GN + j];
    }
    __syncthreads();
    {
        int j = tid & 15, part = tid >> 4;
        float sm = 0.f, sq = 0.f;
        for (int c = part*24; c < part*24 + 24; c++) {
            float v = s[c*17 + j]; sm += v; sq = fmaf(v, v, sq);
        }
        r1[tid] = sm; r2[tid] = sq;
    }
    __syncthreads();
    if (tid < 16) {
        float a = 0.f, q = 0.f;
        #pragma unroll
        for (int p = 0; p < 16; p++) { a += r1[p*16 + tid]; q += r2[p*16 + tid]; }
        float mean = a * (1.f/384.f);
        float var = q * (1.f/384.f) - mean*mean;
        mu[tid] = mean; ri[tid] = rsqrtf(var + 1e-5f);
    }
    __syncthreads();
    float* obase = xn + (size_t)b * CC * GN + n0;
    for (int idx = tid; idx < CC*16; idx += 256) {
        int c = idx >> 4, j = idx & 15;
        obase[(size_t)c * GN + j] = (s[c*17 + j] - mu[j]) * ri[j] * lw[c] + lb[c];
    }
}

// ---------------- launch ----------------
extern "C" void kernel_launch(void* const* d_in, const int* in_sizes, int n_in,
                              void* d_out, int out_size) {
    const float* x      = (const float*)d_in[0];
    const float* bn1_w  = (const float*)d_in[1];
    const float* bn1_b  = (const float*)d_in[2];
    const float* bn1_m  = (const float*)d_in[3];
    const float* bn1_v  = (const float*)d_in[4];
    const float* cw1    = (const float*)d_in[5];
    const float* cb1    = (const float*)d_in[6];
    const float* dw     = (const float*)d_in[7];
    const float* db     = (const float*)d_in[8];
    const float* bn2_w  = (const float*)d_in[9];
    const float* bn2_b  = (const float*)d_in[10];
    const float* bn2_m  = (const float*)d_in[11];
    const float* bn2_v  = (const float*)d_in[12];
    const float* cw2    = (const float*)d_in[13];
    const float* cb2    = (const float*)d_in[14];
    const float* qkv_w  = (const float*)d_in[15];
    const float* proj_w = (const float*)d_in[16];
    const float* proj_b = (const float*)d_in[17];
    const float* ln_w   = (const float*)d_in[18];
    const float* ln_b   = (const float*)d_in[19];
    const float* mlp_w1 = (const float*)d_in[20];
    const float* mlp_b1 = (const float*)d_in[21];
    const float* mlp_w2 = (const float*)d_in[22];
    const float* mlp_b2 = (const float*)d_in[23];

    float *bufA, *bufB, *x1, *x2, *qkvb, *hmid, *w1f, *b1f, *w1t, *w2t;
    cudaGetSymbolAddress((void**)&bufA, g_bufA);
    cudaGetSymbolAddress((void**)&bufB, g_bufB);
    cudaGetSymbolAddress((void**)&x1,   g_x1b);
    cudaGetSymbolAddress((void**)&x2,   g_x2b);
    cudaGetSymbolAddress((void**)&qkvb, g_qkvb);
    cudaGetSymbolAddress((void**)&hmid, g_hmid);
    cudaGetSymbolAddress((void**)&w1f,  g_w1f);
    cudaGetSymbolAddress((void**)&b1f,  g_b1f);
    cudaGetSymbolAddress((void**)&w1t,  g_w1t);
    cudaGetSymbolAddress((void**)&w2t,  g_w2t);

    // weight prep
    fold_bn1_kernel<<<CC, 128>>>(cw1, cb1, bn1_w, bn1_b, bn1_m, bn1_v);
    fold_bn2_kernel<<<2, 192>>>(dw, db, bn2_w, bn2_b, bn2_m, bn2_v);
    transpose_kernel<<<(CC*4*CC + 255)/256, 256>>>(mlp_w1, w1t, CC, 4*CC);    // (384,1536) -> (1536,384)
    transpose_kernel<<<(CC*4*CC + 255)/256, 256>>>(mlp_w2, w2t, 4*CC, CC);    // (1536,384) -> (384,1536)
    zero_kv_kernel<<<(BB*NHEADS*HD*HD + 255)/256, 256>>>();

    // conv path
    run_gemm(w1f, x, b1f, nullptr, bufA, CC, CC, 0);          // h = BN1+1x1
    dwconv_kernel<<<BB*CC, 256>>>(bufA, bufB);                // h2 = dw3x3 + BN2 (folded)
    run_gemm(cw2, bufB, cb2, x, x1, CC, CC, 0);               // x1 = 1x1 + x

    // linear attention
    run_gemm(qkv_w, x1, nullptr, nullptr, qkvb, 3*CC, CC, 0); // qkv
    attn_kv_kernel<<<dim3(BB*NHEADS, 8), 256>>>(qkvb);
    attn_out_kernel<<<dim3(BB*NHEADS, 8), 256>>>(qkvb, bufA); // attn out
    run_gemm(proj_w, bufA, proj_b, x1, x2, CC, CC, 0);        // x2 = proj + x1

    // LN + MLP
    ln_kernel<<<dim3(GN/16, BB), 256>>>(x2, ln_w, ln_b, bufB);          // xn
    run_gemm(w1t, bufB, mlp_b1, nullptr, hmid, 4*CC, CC, 1);            // gelu(fc1)
    run_gemm(w2t, hmid, mlp_b2, x2, (float*)d_out, CC, 4*CC, 0);        // out = x2 + fc2
}